// round 2
// baseline (speedup 1.0000x reference)
#include <cuda_runtime.h>
#include <stdint.h>

#define K 8
#define C 256

// Scratch (allocation-free): stage intermediates + per-split top-8 keys.
static __device__ float g_x1[2 * 1024 * 256];                    // stage0 output
static __device__ float g_x2[2 * 4096 * 256];                    // stage1 output
static __device__ unsigned long long g_keys[2 * 16384 * 64];     // max: 64 keys/query

// ---------------------------------------------------------------------------
// Top-K kernel: one thread per (query, split). Candidates for this split are
// staged in shared memory with precomputed half-squared-norms so the hot-loop
// prune test is a 3-FFMA chain + compare.
//
// dist(q,c) = sqrt(|q-c|^2) + sigmoid(|qn-cn|)  with sigmoid >= 0.5
// prune if  sqrt(d2) + 0.5 >= kth   <=>   (c_h - q.c) >= 0.5*(kth-0.5)^2 - q_h
// where  d2/2 = q_h + c_h - q.c
// ---------------------------------------------------------------------------
template <int SLICE>
__global__ void __launch_bounds__(256) topk_kernel(
    const float* __restrict__ xyzF, const float* __restrict__ nrmF,
    const float* __restrict__ xyzC, const float* __restrict__ nrmC,
    int N, int S, int nsplit)
{
    __shared__ float4 sx[SLICE];
    __shared__ float4 sn[SLICE];

    const int b = blockIdx.z;
    const int split = blockIdx.y;
    const int n = blockIdx.x * 256 + threadIdx.x;
    const int s0 = split * SLICE;

    // Stage candidates into shared memory
    for (int j = threadIdx.x; j < SLICE; j += 256) {
        const float* p = xyzC + ((size_t)b * S + (s0 + j)) * 3;
        float x = p[0], y = p[1], z = p[2];
        sx[j] = make_float4(x, y, z, 0.5f * (x * x + y * y + z * z));
        const float* q = nrmC + ((size_t)b * S + (s0 + j)) * 3;
        float a = q[0], bb = q[1], cc = q[2];
        sn[j] = make_float4(a, bb, cc, 0.5f * (a * a + bb * bb + cc * cc));
    }
    __syncthreads();

    if (n >= N) return;

    const float* p = xyzF + ((size_t)b * N + n) * 3;
    float qx = p[0], qy = p[1], qz = p[2];
    float qh = 0.5f * (qx * qx + qy * qy + qz * qz);
    const float* q = nrmF + ((size_t)b * N + n) * 3;
    float ux = q[0], uy = q[1], uz = q[2];
    float uh = 0.5f * (ux * ux + uy * uy + uz * uz);

    // keys: (dist_bits << 32) | candidate_index. Sentinel = FLT_MAX dist.
    unsigned long long key[K];
#pragma unroll
    for (int i = 0; i < K; i++) key[i] = 0x7F7FFFFFFFFFFFFFULL;
    float kth = 3.402823466e38f;
    float t0 = kth - 0.5f;
    float pr = fmaf(0.5f * t0, t0, -qh);  // +inf: evaluate everything at first

#pragma unroll 4
    for (int j = 0; j < SLICE; j++) {
        float4 c = sx[j];
        // sdot = c_h - q.c   (monotone in d2)
        float sdot = fmaf(-qz, c.z, fmaf(-qy, c.y, fmaf(-qx, c.x, c.w)));
        if (sdot < pr) {
            float d2 = fmaxf(2.0f * (sdot + qh), 0.0f);
            float dx = sqrtf(d2);
            float4 nn = sn[j];
            float sd = fmaf(-uz, nn.z, fmaf(-uy, nn.y, fmaf(-ux, nn.x, nn.w)));
            float dn2 = fmaxf(2.0f * (sd + uh), 0.0f);
            float dn = sqrtf(dn2);
            float sig = 1.0f / (1.0f + __expf(-dn));
            float tot = dx + sig;
            if (tot < kth) {
                unsigned long long nk =
                    ((unsigned long long)__float_as_uint(tot) << 32) |
                    (unsigned)(s0 + j);
                // replace current max among the 8
                unsigned long long mv = key[0];
                int mi = 0;
#pragma unroll
                for (int i = 1; i < K; i++)
                    if (key[i] > mv) { mv = key[i]; mi = i; }
                key[mi] = nk;
                // recompute max -> new kth & prune threshold
                mv = key[0];
#pragma unroll
                for (int i = 1; i < K; i++)
                    if (key[i] > mv) mv = key[i];
                kth = __uint_as_float((unsigned)(mv >> 32));
                float t = kth - 0.5f;
                pr = fmaf(0.5f * t, t, -qh);
            }
        }
    }

    unsigned long long* o = g_keys + (((size_t)b * N + n) * nsplit + split) * K;
#pragma unroll
    for (int i = 0; i < K; i++) o[i] = key[i];
}

// ---------------------------------------------------------------------------
// Merge + interpolate kernel: one block (256 threads = C channels) per query.
// Merges nsplit*8 partial keys, computes inverse-distance weights from the
// exact stored fp32 distances, gathers 8 coarse feature rows, merges with p1.
// ---------------------------------------------------------------------------
__global__ void __launch_bounds__(256) interp_kernel(
    const float* __restrict__ p1, const float* __restrict__ p2,
    float* __restrict__ out, int N, int S, int M)
{
    const int b = blockIdx.y;
    const int n = blockIdx.x;
    const int tid = threadIdx.x;

    __shared__ unsigned long long sk[64];
    __shared__ float sw[K];
    __shared__ int sidx[K];

    const unsigned long long* kq = g_keys + ((size_t)b * N + n) * (size_t)M;
    if (tid < M) sk[tid] = kq[tid];
    __syncthreads();

    if (tid == 0) {
        // partial selection sort: 8 smallest u64 keys to the front
        for (int i = 0; i < K; i++) {
            int mi = i;
            unsigned long long mv = sk[i];
            for (int j = i + 1; j < M; j++)
                if (sk[j] < mv) { mv = sk[j]; mi = j; }
            unsigned long long t = sk[i];
            sk[i] = mv;
            sk[mi] = t;
        }
    }
    __syncthreads();

    if (tid < K) {
        unsigned long long k = sk[tid];
        float d = __uint_as_float((unsigned)(k >> 32));
        float r = 1.0f / (d + 1e-8f);
        float rs = r;
#pragma unroll
        for (int off = 1; off < 8; off <<= 1)
            rs += __shfl_xor_sync(0xFFu, rs, off);
        sw[tid] = r / rs;
        sidx[tid] = (int)(unsigned)(k & 0xFFFFFFFFu);
    }
    __syncthreads();

    float acc = 0.0f;
#pragma unroll
    for (int k = 0; k < K; k++)
        acc = fmaf(sw[k], p2[((size_t)b * S + sidx[k]) * C + tid], acc);

    float pv = p1[((size_t)b * N + n) * C + tid];
    out[((size_t)b * N + n) * C + tid] =
        (fmaxf(pv, acc) + (pv + acc) * 0.5f) * 0.5f;
}

// ---------------------------------------------------------------------------
extern "C" void kernel_launch(void* const* d_in, const int* in_sizes, int n_in,
                              void* d_out, int out_size)
{
    // Inputs are interleaved per resolution (dict insertion order in
    // setup_inputs): xyz0, nrm0, feat0, xyz1, nrm1, feat1, ...
    // Classify robustly by element count: per resolution N, the two 6N
    // tensors are xyz then nrm (encounter order); the 512N tensor is feat.
    const int B = 2;
    const int Ns[4] = {16384, 4096, 1024, 256};
    const float* xyz[4] = {0, 0, 0, 0};
    const float* nrm[4] = {0, 0, 0, 0};
    const float* feat[4] = {0, 0, 0, 0};

    for (int i = 0; i < n_in; i++) {
        long long cnt = in_sizes[i];
        for (int r = 0; r < 4; r++) {
            long long small = (long long)B * Ns[r] * 3;
            long long big = (long long)B * Ns[r] * C;
            if (cnt == small) {
                if (!xyz[r]) xyz[r] = (const float*)d_in[i];
                else if (!nrm[r]) nrm[r] = (const float*)d_in[i];
                break;
            } else if (cnt == big) {
                if (!feat[r]) feat[r] = (const float*)d_in[i];
                break;
            }
        }
    }

    float* out = (float*)d_out;
    float *x1, *x2;
    cudaGetSymbolAddress((void**)&x1, g_x1);
    cudaGetSymbolAddress((void**)&x2, g_x2);

    // ---- Stage 0: fine=xyz2 (N=1024), coarse=xyz3 (S=256), p1=feat2, p2=feat3
    {
        const int N = 1024, S = 256, NS = 4;  // slice = 64
        topk_kernel<64><<<dim3(N / 256, NS, B), 256>>>(xyz[2], nrm[2], xyz[3], nrm[3], N, S, NS);
        interp_kernel<<<dim3(N, B), 256>>>(feat[2], feat[3], x1, N, S, NS * K);
    }
    // ---- Stage 1: fine=xyz1 (N=4096), coarse=xyz2 (S=1024), p1=feat1, p2=x1
    {
        const int N = 4096, S = 1024, NS = 8;  // slice = 128
        topk_kernel<128><<<dim3(N / 256, NS, B), 256>>>(xyz[1], nrm[1], xyz[2], nrm[2], N, S, NS);
        interp_kernel<<<dim3(N, B), 256>>>(feat[1], x1, x2, N, S, NS * K);
    }
    // ---- Stage 2: fine=xyz0 (N=16384), coarse=xyz1 (S=4096), p1=feat0, p2=x2
    {
        const int N = 16384, S = 4096, NS = 8;  // slice = 512
        topk_kernel<512><<<dim3(N / 256, NS, B), 256>>>(xyz[0], nrm[0], xyz[1], nrm[1], N, S, NS);
        interp_kernel<<<dim3(N, B), 256>>>(feat[0], x2, out, N, S, NS * K);
    }
}

// round 3
// speedup vs baseline: 1.7672x; 1.7672x over previous
#include <cuda_runtime.h>
#include <stdint.h>

#define K 8
#define C 256

// ---------------------------------------------------------------------------
// Scratch (allocation-free)
// ---------------------------------------------------------------------------
static __device__ float4 g_cx[2 * 4096];            // packed coarse xyz + 0.5*|.|^2
static __device__ float4 g_cn[2 * 4096];            // packed coarse nrm + 0.5*|.|^2
static __device__ float  g_wiv[2 * 16384 * 16];     // per query: w[8], idx-bits[8]
static __device__ float  g_x1[2 * 1024 * 256];      // stage0 output
static __device__ float  g_x2[2 * 4096 * 256];      // stage1 output

// ---------------------------------------------------------------------------
// Pack coarse points into float4 with precomputed half-squared-norm.
// ---------------------------------------------------------------------------
__global__ void pack_kernel(const float* __restrict__ xyz,
                            const float* __restrict__ nrm, int tot)
{
    int i = blockIdx.x * 256 + threadIdx.x;
    if (i >= tot) return;
    float x = xyz[3 * i], y = xyz[3 * i + 1], z = xyz[3 * i + 2];
    g_cx[i] = make_float4(x, y, z, 0.5f * (x * x + y * y + z * z));
    float a = nrm[3 * i], b = nrm[3 * i + 1], c = nrm[3 * i + 2];
    g_cn[i] = make_float4(a, b, c, 0.5f * (a * a + b * b + c * c));
}

// ---------------------------------------------------------------------------
// Warp-per-query top-K with a warp-shared (lane-replicated) sorted top-8.
//
// dist(q,c) = sqrt(|q-c|^2) + sigmoid(|qn-cn|),  sigmoid >= 0.5
// lower-bound prune:  candidate can beat kth only if
//   sdot = c_h - q.c  <  0.5*(kth-0.5)^2 - q_h   (= pr)
//
// Lanes sweep 32 candidates per step; survivors (ballot) are broadcast and
// inserted uniformly into the replicated sorted array. Emits normalized
// inverse-distance weights + indices directly.
// ---------------------------------------------------------------------------
template <int S>
__global__ void __launch_bounds__(256) topk_kernel(
    const float* __restrict__ xyzF, const float* __restrict__ nrmF,
    int N, int b)
{
    const int lane = threadIdx.x & 31;
    const int n = blockIdx.x * 8 + (threadIdx.x >> 5);
    if (n >= N) return;

    const float4* __restrict__ cx = g_cx + b * S;
    const float4* __restrict__ cn = g_cn + b * S;

    const float* p = xyzF + ((size_t)b * N + n) * 3;
    const float qx = p[0], qy = p[1], qz = p[2];
    const float qh = 0.5f * (qx * qx + qy * qy + qz * qz);
    const float* q = nrmF + ((size_t)b * N + n) * 3;
    const float ux = q[0], uy = q[1], uz = q[2];
    const float uh = 0.5f * (ux * ux + uy * uy + uz * uz);

    float d[K];
    int   ix[K];
#pragma unroll
    for (int i = 0; i < K; i++) { d[i] = 3.402823466e38f; ix[i] = 0; }
    float kth = 3.402823466e38f;
    float pr  = __int_as_float(0x7F800000);  // +inf: evaluate everything first

    for (int base = 0; base < S; base += 32) {
        float4 c = __ldg(cx + base + lane);
        float sdot = fmaf(-qz, c.z, fmaf(-qy, c.y, fmaf(-qx, c.x, c.w)));
        unsigned m = __ballot_sync(0xFFFFFFFFu, sdot < pr);
        if (m) {
            float tot = 3.402823466e38f;
            if (sdot < pr) {
                float dxy = sqrtf(fmaxf(2.0f * (sdot + qh), 0.0f));
                float4 nc = __ldg(cn + base + lane);
                float sd = fmaf(-uz, nc.z, fmaf(-uy, nc.y, fmaf(-ux, nc.x, nc.w)));
                float dn = sqrtf(fmaxf(2.0f * (sd + uh), 0.0f));
                tot = dxy + 1.0f / (1.0f + __expf(-dn));
            }
            while (m) {
                int src = __ffs(m) - 1;
                m &= m - 1;
                float td = __shfl_sync(0xFFFFFFFFu, tot, src);
                if (td < kth) {                 // warp-uniform
                    float cd = td;
                    int   ci = base + src;
#pragma unroll
                    for (int i = 0; i < K; i++) {
                        float od = d[i]; int oi = ix[i];
                        bool sw = cd < od;
                        d[i]  = sw ? cd : od;
                        ix[i] = sw ? ci : oi;
                        cd = sw ? od : cd;
                        ci = sw ? oi : ci;
                    }
                    kth = d[K - 1];
                    float t = kth - 0.5f;
                    pr = fmaf(0.5f * t, t, -qh);
                }
            }
        }
    }

    if (lane == 0) {
        float r[K];
        float sum = 0.0f;
#pragma unroll
        for (int i = 0; i < K; i++) { r[i] = 1.0f / (d[i] + 1e-8f); sum += r[i]; }
        float inv = 1.0f / sum;
        float* o = g_wiv + ((size_t)b * N + n) * 16;
        float4* o4 = (float4*)o;
        o4[0] = make_float4(r[0] * inv, r[1] * inv, r[2] * inv, r[3] * inv);
        o4[1] = make_float4(r[4] * inv, r[5] * inv, r[6] * inv, r[7] * inv);
        o4[2] = make_float4(__int_as_float(ix[0]), __int_as_float(ix[1]),
                            __int_as_float(ix[2]), __int_as_float(ix[3]));
        o4[3] = make_float4(__int_as_float(ix[4]), __int_as_float(ix[5]),
                            __int_as_float(ix[6]), __int_as_float(ix[7]));
    }
}

// ---------------------------------------------------------------------------
// Interpolate: block (256 threads = channels) per query. Pure gather + merge.
// ---------------------------------------------------------------------------
__global__ void __launch_bounds__(256) interp_kernel(
    const float* __restrict__ p1, const float* __restrict__ p2,
    float* __restrict__ out, int N, int S)
{
    const int b = blockIdx.y;
    const int n = blockIdx.x;
    const int tid = threadIdx.x;

    const float4* wv = (const float4*)(g_wiv + ((size_t)b * N + n) * 16);
    float4 w0 = __ldg(wv + 0), w1 = __ldg(wv + 1);
    float4 f0 = __ldg(wv + 2), f1 = __ldg(wv + 3);

    const float* P = p2 + (size_t)b * S * C;
    float acc;
    acc = w0.x * __ldg(P + (size_t)__float_as_int(f0.x) * C + tid);
    acc = fmaf(w0.y, __ldg(P + (size_t)__float_as_int(f0.y) * C + tid), acc);
    acc = fmaf(w0.z, __ldg(P + (size_t)__float_as_int(f0.z) * C + tid), acc);
    acc = fmaf(w0.w, __ldg(P + (size_t)__float_as_int(f0.w) * C + tid), acc);
    acc = fmaf(w1.x, __ldg(P + (size_t)__float_as_int(f1.x) * C + tid), acc);
    acc = fmaf(w1.y, __ldg(P + (size_t)__float_as_int(f1.y) * C + tid), acc);
    acc = fmaf(w1.z, __ldg(P + (size_t)__float_as_int(f1.z) * C + tid), acc);
    acc = fmaf(w1.w, __ldg(P + (size_t)__float_as_int(f1.w) * C + tid), acc);

    const size_t qo = ((size_t)b * N + n) * C + tid;
    float pv = __ldg(p1 + qo);
    out[qo] = (fmaxf(pv, acc) + (pv + acc) * 0.5f) * 0.5f;
}

// ---------------------------------------------------------------------------
extern "C" void kernel_launch(void* const* d_in, const int* in_sizes, int n_in,
                              void* d_out, int out_size)
{
    // Classify inputs by element count (interleaved per resolution):
    // per resolution N, the two 6N tensors are xyz then nrm; 512N is feat.
    const int B = 2;
    const int Ns[4] = {16384, 4096, 1024, 256};
    const float* xyz[4] = {0, 0, 0, 0};
    const float* nrm[4] = {0, 0, 0, 0};
    const float* feat[4] = {0, 0, 0, 0};

    for (int i = 0; i < n_in; i++) {
        long long cnt = in_sizes[i];
        for (int r = 0; r < 4; r++) {
            long long small = (long long)B * Ns[r] * 3;
            long long big = (long long)B * Ns[r] * C;
            if (cnt == small) {
                if (!xyz[r]) xyz[r] = (const float*)d_in[i];
                else if (!nrm[r]) nrm[r] = (const float*)d_in[i];
                break;
            } else if (cnt == big) {
                if (!feat[r]) feat[r] = (const float*)d_in[i];
                break;
            }
        }
    }

    float* out = (float*)d_out;
    float *x1, *x2;
    cudaGetSymbolAddress((void**)&x1, g_x1);
    cudaGetSymbolAddress((void**)&x2, g_x2);

    // ---- Stage 0: fine N=1024 (xyz2), coarse S=256 (xyz3), p1=feat2, p2=feat3
    {
        const int N = 1024, S = 256;
        pack_kernel<<<(B * S + 255) / 256, 256>>>(xyz[3], nrm[3], B * S);
        topk_kernel<S><<<N / 8, 256>>>(xyz[2], nrm[2], N, 0);
        topk_kernel<S><<<N / 8, 256>>>(xyz[2], nrm[2], N, 1);
        interp_kernel<<<dim3(N, B), 256>>>(feat[2], feat[3], x1, N, S);
    }
    // ---- Stage 1: fine N=4096 (xyz1), coarse S=1024 (xyz2), p1=feat1, p2=x1
    {
        const int N = 4096, S = 1024;
        pack_kernel<<<(B * S + 255) / 256, 256>>>(xyz[2], nrm[2], B * S);
        topk_kernel<S><<<N / 8, 256>>>(xyz[1], nrm[1], N, 0);
        topk_kernel<S><<<N / 8, 256>>>(xyz[1], nrm[1], N, 1);
        interp_kernel<<<dim3(N, B), 256>>>(feat[1], x1, x2, N, S);
    }
    // ---- Stage 2: fine N=16384 (xyz0), coarse S=4096 (xyz1), p1=feat0, p2=x2
    {
        const int N = 16384, S = 4096;
        pack_kernel<<<(B * S + 255) / 256, 256>>>(xyz[1], nrm[1], B * S);
        topk_kernel<S><<<N / 8, 256>>>(xyz[0], nrm[0], N, 0);
        topk_kernel<S><<<N / 8, 256>>>(xyz[0], nrm[0], N, 1);
        interp_kernel<<<dim3(N, B), 256>>>(feat[0], x2, out, N, S);
    }
}

// round 4
// speedup vs baseline: 2.3350x; 1.3213x over previous
#include <cuda_runtime.h>
#include <stdint.h>

#define K 8
#define C 256
#define INF_F __int_as_float(0x7F800000)

// ---------------------------------------------------------------------------
// Scratch (allocation-free)
// ---------------------------------------------------------------------------
static __device__ float4 g_cx[2 * 4096];            // packed coarse xyz + 0.5*|.|^2
static __device__ float4 g_cn[2 * 4096];            // packed coarse nrm + 0.5*|.|^2
static __device__ float  g_wiv[2 * 16384 * 16];     // per query: w[8], idx-bits[8]
static __device__ float  g_x1[2 * 1024 * 256];      // stage0 output
static __device__ float  g_x2[2 * 4096 * 256];      // stage1 output

// ---------------------------------------------------------------------------
__global__ void pack_kernel(const float* __restrict__ xyz,
                            const float* __restrict__ nrm, int tot)
{
    int i = blockIdx.x * 256 + threadIdx.x;
    if (i >= tot) return;
    float x = xyz[3 * i], y = xyz[3 * i + 1], z = xyz[3 * i + 2];
    g_cx[i] = make_float4(x, y, z, 0.5f * (x * x + y * y + z * z));
    float a = nrm[3 * i], b = nrm[3 * i + 1], c = nrm[3 * i + 2];
    g_cn[i] = make_float4(a, b, c, 0.5f * (a * a + b * b + c * c));
}

// ---------------------------------------------------------------------------
// Warp-per-query top-K, warp-shared sorted top-8.
//   dist(q,c) = sqrt(|q-c|^2) + sigmoid(|qn-cn|),  sigmoid >= 0.5
//   prune:  sdot = c_h - q.c < 0.5*(kth-0.5)^2 - q_h
// Warm-up: first 32 candidates evaluated in parallel, top-8 via shfl-min.
// Main: 2x-unrolled prune sweep; survivors re-balloted on the exact distance;
// insertion is a branchless sorted bubble (no-op for stale bits).
// ---------------------------------------------------------------------------
template <int S>
__global__ void __launch_bounds__(256) topk_kernel(
    const float* __restrict__ xyzF, const float* __restrict__ nrmF, int N)
{
    const int lane = threadIdx.x & 31;
    const int b = blockIdx.y;
    const int n = blockIdx.x * 8 + (threadIdx.x >> 5);
    if (n >= N) return;

    const float4* __restrict__ cx = g_cx + b * S;
    const float4* __restrict__ cn = g_cn + b * S;

    const float* p = xyzF + ((size_t)b * N + n) * 3;
    const float qx = p[0], qy = p[1], qz = p[2];
    const float qh = 0.5f * (qx * qx + qy * qy + qz * qz);
    const float* q = nrmF + ((size_t)b * N + n) * 3;
    const float ux = q[0], uy = q[1], uz = q[2];
    const float uh = 0.5f * (ux * ux + uy * uy + uz * uz);

    float d[K];
    int   ix[K];

    // ---- Warm-up: candidates 0..31, full eval, 8x shfl-min extraction ----
    float tot;
    {
        float4 c = __ldg(cx + lane);
        float sd = fmaf(-qz, c.z, fmaf(-qy, c.y, fmaf(-qx, c.x, c.w)));
        float dxy = sqrtf(fmaxf(2.0f * (sd + qh), 0.0f));
        float4 nc = __ldg(cn + lane);
        float nd = fmaf(-uz, nc.z, fmaf(-uy, nc.y, fmaf(-ux, nc.x, nc.w)));
        float dn = sqrtf(fmaxf(2.0f * (nd + uh), 0.0f));
        tot = dxy + 1.0f / (1.0f + __expf(-dn));
    }
    {
        float v = tot;
        int vi = lane;
#pragma unroll
        for (int r = 0; r < K; r++) {
            float mv = v;
            int mi = vi;
#pragma unroll
            for (int off = 16; off; off >>= 1) {
                float ov = __shfl_xor_sync(0xFFFFFFFFu, mv, off);
                int oi = __shfl_xor_sync(0xFFFFFFFFu, mi, off);
                if (ov < mv || (ov == mv && oi < mi)) { mv = ov; mi = oi; }
            }
            d[r] = mv;
            ix[r] = mi;
            if (vi == mi) v = INF_F;  // winner's lane retires its candidate
        }
    }
    float kth = d[K - 1];
    float tt0 = kth - 0.5f;
    float pr = fmaf(0.5f * tt0, tt0, -qh);

    // ---- Main sweep ----
#define PROCESS(GB, SD)                                                        \
    {                                                                          \
        unsigned m_ = __ballot_sync(0xFFFFFFFFu, (SD) < pr);                   \
        if (m_) {                                                              \
            float te = INF_F;                                                  \
            if ((SD) < pr) {                                                   \
                float dxy = sqrtf(fmaxf(2.0f * ((SD) + qh), 0.0f));            \
                float4 nc = __ldg(cn + (GB) + lane);                           \
                float nd = fmaf(-uz, nc.z,                                     \
                                fmaf(-uy, nc.y, fmaf(-ux, nc.x, nc.w)));       \
                float dn = sqrtf(fmaxf(2.0f * (nd + uh), 0.0f));               \
                te = dxy + 1.0f / (1.0f + __expf(-dn));                        \
            }                                                                  \
            unsigned m2 = __ballot_sync(0xFFFFFFFFu, te < kth);                \
            while (m2) {                                                       \
                int src = __ffs(m2) - 1;                                       \
                m2 &= m2 - 1;                                                  \
                float cd = __shfl_sync(0xFFFFFFFFu, te, src);                  \
                int ci = (GB) + src;                                           \
                _Pragma("unroll") for (int i = 0; i < K; i++)                  \
                {                                                              \
                    bool sw = cd < d[i];                                       \
                    float od = d[i];                                           \
                    int oi = ix[i];                                            \
                    d[i] = sw ? cd : od;                                       \
                    ix[i] = sw ? ci : oi;                                      \
                    cd = sw ? od : cd;                                         \
                    ci = sw ? oi : ci;                                         \
                }                                                              \
            }                                                                  \
            kth = d[K - 1];                                                    \
            float t_ = kth - 0.5f;                                             \
            pr = fmaf(0.5f * t_, t_, -qh);                                     \
        }                                                                      \
    }

    int base = 32;
    for (; base + 64 <= S; base += 64) {
        float4 c0 = __ldg(cx + base + lane);
        float4 c1 = __ldg(cx + base + 32 + lane);
        float s0 = fmaf(-qz, c0.z, fmaf(-qy, c0.y, fmaf(-qx, c0.x, c0.w)));
        float s1 = fmaf(-qz, c1.z, fmaf(-qy, c1.y, fmaf(-qx, c1.x, c1.w)));
        PROCESS(base, s0);
        PROCESS(base + 32, s1);
    }
    for (; base < S; base += 32) {
        float4 c0 = __ldg(cx + base + lane);
        float s0 = fmaf(-qz, c0.z, fmaf(-qy, c0.y, fmaf(-qx, c0.x, c0.w)));
        PROCESS(base, s0);
    }
#undef PROCESS

    if (lane == 0) {
        float r[K];
        float sum = 0.0f;
#pragma unroll
        for (int i = 0; i < K; i++) { r[i] = 1.0f / (d[i] + 1e-8f); sum += r[i]; }
        float inv = 1.0f / sum;
        float4* o4 = (float4*)(g_wiv + ((size_t)b * N + n) * 16);
        o4[0] = make_float4(r[0] * inv, r[1] * inv, r[2] * inv, r[3] * inv);
        o4[1] = make_float4(r[4] * inv, r[5] * inv, r[6] * inv, r[7] * inv);
        o4[2] = make_float4(__int_as_float(ix[0]), __int_as_float(ix[1]),
                            __int_as_float(ix[2]), __int_as_float(ix[3]));
        o4[3] = make_float4(__int_as_float(ix[4]), __int_as_float(ix[5]),
                            __int_as_float(ix[6]), __int_as_float(ix[7]));
    }
}

// ---------------------------------------------------------------------------
// Interpolate: 64 lanes (float4 channels) per query, 4 queries per block.
// ---------------------------------------------------------------------------
__global__ void __launch_bounds__(256) interp_kernel(
    const float* __restrict__ p1, const float* __restrict__ p2,
    float* __restrict__ out, int N, int S)
{
    const int b = blockIdx.y;
    const int g = threadIdx.x >> 6;
    const int l = threadIdx.x & 63;
    const int n = blockIdx.x * 4 + g;

    const float4* wv = (const float4*)(g_wiv + ((size_t)b * N + n) * 16);
    float4 w0 = __ldg(wv + 0), w1 = __ldg(wv + 1);
    float4 f0 = __ldg(wv + 2), f1 = __ldg(wv + 3);

    const float4* __restrict__ P = (const float4*)p2 + (size_t)b * S * (C / 4);
    float4 acc;
    {
        float4 r0 = __ldg(P + (size_t)__float_as_int(f0.x) * (C / 4) + l);
        acc.x = w0.x * r0.x; acc.y = w0.x * r0.y;
        acc.z = w0.x * r0.z; acc.w = w0.x * r0.w;
    }
#define GATHER(W, IDX)                                                         \
    {                                                                          \
        float4 r_ = __ldg(P + (size_t)__float_as_int(IDX) * (C / 4) + l);      \
        acc.x = fmaf(W, r_.x, acc.x); acc.y = fmaf(W, r_.y, acc.y);            \
        acc.z = fmaf(W, r_.z, acc.z); acc.w = fmaf(W, r_.w, acc.w);            \
    }
    GATHER(w0.y, f0.y) GATHER(w0.z, f0.z) GATHER(w0.w, f0.w)
    GATHER(w1.x, f1.x) GATHER(w1.y, f1.y) GATHER(w1.z, f1.z) GATHER(w1.w, f1.w)
#undef GATHER

    const size_t qo = ((size_t)b * N + n) * (C / 4) + l;
    float4 pv = __ldg((const float4*)p1 + qo);
    float4 o;
    o.x = (fmaxf(pv.x, acc.x) + (pv.x + acc.x) * 0.5f) * 0.5f;
    o.y = (fmaxf(pv.y, acc.y) + (pv.y + acc.y) * 0.5f) * 0.5f;
    o.z = (fmaxf(pv.z, acc.z) + (pv.z + acc.z) * 0.5f) * 0.5f;
    o.w = (fmaxf(pv.w, acc.w) + (pv.w + acc.w) * 0.5f) * 0.5f;
    ((float4*)out)[qo] = o;
}

// ---------------------------------------------------------------------------
extern "C" void kernel_launch(void* const* d_in, const int* in_sizes, int n_in,
                              void* d_out, int out_size)
{
    // Classify inputs by element count (interleaved per resolution):
    // per resolution N, the two 6N tensors are xyz then nrm; 512N is feat.
    const int B = 2;
    const int Ns[4] = {16384, 4096, 1024, 256};
    const float* xyz[4] = {0, 0, 0, 0};
    const float* nrm[4] = {0, 0, 0, 0};
    const float* feat[4] = {0, 0, 0, 0};

    for (int i = 0; i < n_in; i++) {
        long long cnt = in_sizes[i];
        for (int r = 0; r < 4; r++) {
            long long small = (long long)B * Ns[r] * 3;
            long long big = (long long)B * Ns[r] * C;
            if (cnt == small) {
                if (!xyz[r]) xyz[r] = (const float*)d_in[i];
                else if (!nrm[r]) nrm[r] = (const float*)d_in[i];
                break;
            } else if (cnt == big) {
                if (!feat[r]) feat[r] = (const float*)d_in[i];
                break;
            }
        }
    }

    float* out = (float*)d_out;
    float *x1, *x2;
    cudaGetSymbolAddress((void**)&x1, g_x1);
    cudaGetSymbolAddress((void**)&x2, g_x2);

    // ---- Stage 0: fine N=1024 (xyz2), coarse S=256 (xyz3)
    {
        const int N = 1024, S = 256;
        pack_kernel<<<(B * S + 255) / 256, 256>>>(xyz[3], nrm[3], B * S);
        topk_kernel<S><<<dim3(N / 8, B), 256>>>(xyz[2], nrm[2], N);
        interp_kernel<<<dim3(N / 4, B), 256>>>(feat[2], feat[3], x1, N, S);
    }
    // ---- Stage 1: fine N=4096 (xyz1), coarse S=1024 (xyz2)
    {
        const int N = 4096, S = 1024;
        pack_kernel<<<(B * S + 255) / 256, 256>>>(xyz[2], nrm[2], B * S);
        topk_kernel<S><<<dim3(N / 8, B), 256>>>(xyz[1], nrm[1], N);
        interp_kernel<<<dim3(N / 4, B), 256>>>(feat[1], x1, x2, N, S);
    }
    // ---- Stage 2: fine N=16384 (xyz0), coarse S=4096 (xyz1)
    {
        const int N = 16384, S = 4096;
        pack_kernel<<<(B * S + 255) / 256, 256>>>(xyz[1], nrm[1], B * S);
        topk_kernel<S><<<dim3(N / 8, B), 256>>>(xyz[0], nrm[0], N);
        interp_kernel<<<dim3(N / 4, B), 256>>>(feat[0], x2, out, N, S);
    }
}

// round 5
// speedup vs baseline: 2.5659x; 1.0989x over previous
#include <cuda_runtime.h>
#include <stdint.h>

#define K 8
#define C 256
#define INF_F __int_as_float(0x7F800000)

// ---------------------------------------------------------------------------
// Scratch (allocation-free). Point regions: stage2 [0,8192), stage1 [8192,10240),
// stage0 [10240,10752). Group regions: stage2 [0,256), stage1 [256,320), stage0 [320,336).
// ---------------------------------------------------------------------------
static __device__ float4 g_cx[10752];              // packed xyz + 0.5|.|^2 (orig order)
static __device__ float4 g_cn[10752];              // packed nrm + 0.5|.|^2
static __device__ unsigned long long g_code[10752];// morton<<32 | local idx
static __device__ float4 g_sx[10752];              // sorted xyz
static __device__ float4 g_sn[10752];              // sorted nrm
static __device__ int    g_sid[10752];             // sorted pos -> original local idx
static __device__ float4 g_gc[336];                // group center + radius
static __device__ float  g_wiv[2 * 16384 * 16 + 2 * 4096 * 16 + 2 * 1024 * 16];
static __device__ float  g_x1[2 * 1024 * 256];     // stage0 output
static __device__ float  g_x2[2 * 4096 * 256];     // stage1 output

#define WOFF2 0
#define WOFF1 (2 * 16384 * 16)
#define WOFF0 (2 * 16384 * 16 + 2 * 4096 * 16)

// ---------------------------------------------------------------------------
__device__ __forceinline__ unsigned expand_bits(unsigned v) {
    v &= 0x3FFu;
    v = (v | (v << 16)) & 0x030000FFu;
    v = (v | (v << 8))  & 0x0300F00Fu;
    v = (v | (v << 4))  & 0x030C30C3u;
    v = (v | (v << 2))  & 0x09249249u;
    return v;
}

__device__ __forceinline__ unsigned quant10(float x) {
    float u = (x + 4.2f) * (1024.0f / 8.4f);
    u = fminf(fmaxf(u, 0.0f), 1023.0f);
    return (unsigned)u;
}

// Pack + morton code. tot = B*S elements, local idx = i & (S-1).
__global__ void pack_kernel(const float* __restrict__ xyz,
                            const float* __restrict__ nrm,
                            int tot, int Smask, int base)
{
    int i = blockIdx.x * 256 + threadIdx.x;
    if (i >= tot) return;
    float x = xyz[3 * i], y = xyz[3 * i + 1], z = xyz[3 * i + 2];
    g_cx[base + i] = make_float4(x, y, z, 0.5f * (x * x + y * y + z * z));
    float a = nrm[3 * i], b = nrm[3 * i + 1], c = nrm[3 * i + 2];
    g_cn[base + i] = make_float4(a, b, c, 0.5f * (a * a + b * b + c * c));
    unsigned code = (expand_bits(quant10(x)) << 2) |
                    (expand_bits(quant10(y)) << 1) |
                     expand_bits(quant10(z));
    g_code[base + i] = ((unsigned long long)code << 32) | (unsigned)(i & Smask);
}

// In-smem bitonic sort of one batch segment (S power of two).
template <int S, int THR>
__global__ void __launch_bounds__(THR) sort_kernel(int base)
{
    __shared__ unsigned long long a[S];
    const int seg = base + blockIdx.x * S;
    for (int i = threadIdx.x; i < S; i += THR) a[i] = g_code[seg + i];
    __syncthreads();
#pragma unroll 1
    for (int k = 2; k <= S; k <<= 1) {
#pragma unroll 1
        for (int j = k >> 1; j > 0; j >>= 1) {
            for (int i = threadIdx.x; i < S; i += THR) {
                int l = i ^ j;
                if (l > i) {
                    bool up = (i & k) == 0;
                    unsigned long long x = a[i], y = a[l];
                    if ((x > y) == up) { a[i] = y; a[l] = x; }
                }
            }
            __syncthreads();
        }
    }
    for (int i = threadIdx.x; i < S; i += THR) g_code[seg + i] = a[i];
}

// Reorder into sorted arrays + per-32-point group bounding spheres.
template <int S, int G>
__global__ void __launch_bounds__(256) reorder_kernel(int base, int gbase, int TG)
{
    int w = (blockIdx.x * 256 + threadIdx.x) >> 5;
    int lane = threadIdx.x & 31;
    if (w >= TG) return;
    int bseg = w / G, gi = w % G;
    int sb = base + bseg * S;

    unsigned long long key = g_code[sb + gi * 32 + lane];
    int li = (int)(unsigned)key;
    float4 v = g_cx[sb + li];
    int dst = sb + gi * 32 + lane;
    g_sx[dst] = v;
    g_sn[dst] = g_cn[sb + li];
    g_sid[dst] = li;

    float mnx = v.x, mxx = v.x, mny = v.y, mxy = v.y, mnz = v.z, mxz = v.z;
#pragma unroll
    for (int off = 16; off; off >>= 1) {
        mnx = fminf(mnx, __shfl_xor_sync(0xFFFFFFFFu, mnx, off));
        mxx = fmaxf(mxx, __shfl_xor_sync(0xFFFFFFFFu, mxx, off));
        mny = fminf(mny, __shfl_xor_sync(0xFFFFFFFFu, mny, off));
        mxy = fmaxf(mxy, __shfl_xor_sync(0xFFFFFFFFu, mxy, off));
        mnz = fminf(mnz, __shfl_xor_sync(0xFFFFFFFFu, mnz, off));
        mxz = fmaxf(mxz, __shfl_xor_sync(0xFFFFFFFFu, mxz, off));
    }
    float cxc = (mnx + mxx) * 0.5f, cyc = (mny + mxy) * 0.5f, czc = (mnz + mxz) * 0.5f;
    float dx = v.x - cxc, dy = v.y - cyc, dz = v.z - czc;
    float d2 = fmaf(dx, dx, fmaf(dy, dy, dz * dz));
#pragma unroll
    for (int off = 16; off; off >>= 1)
        d2 = fmaxf(d2, __shfl_xor_sync(0xFFFFFFFFu, d2, off));
    if (lane == 0) g_gc[gbase + w] = make_float4(cxc, cyc, czc, sqrtf(d2));
}

// ---------------------------------------------------------------------------
// topk v2: warp per query, group-pruned sweep.
// ---------------------------------------------------------------------------
template <int S, int G>
__global__ void __launch_bounds__(256) topk_kernel(
    const float* __restrict__ xyzF, const float* __restrict__ nrmF,
    int N, int base, int gbase, int wbase)
{
    const int lane = threadIdx.x & 31;
    const int b = blockIdx.y;
    const int n = blockIdx.x * 8 + (threadIdx.x >> 5);
    if (n >= N) return;

    const float4* __restrict__ sx = g_sx + base + b * S;
    const float4* __restrict__ sn = g_sn + base + b * S;
    const float4* __restrict__ gc = g_gc + gbase + b * G;

    const float* p = xyzF + ((size_t)b * N + n) * 3;
    const float qx = p[0], qy = p[1], qz = p[2];
    const float qh = 0.5f * (qx * qx + qy * qy + qz * qz);
    const float* q = nrmF + ((size_t)b * N + n) * 3;
    const float ux = q[0], uy = q[1], uz = q[2];
    const float uh = 0.5f * (ux * ux + uy * uy + uz * uz);

    constexpr int GS = (G + 31) / 32;
    float d2c[GS], rr[GS];

    // ---- Phase 1: distances to all group centers; find nearest group ----
    float bd2 = INF_F;
    int bg = 0;
#pragma unroll
    for (int s = 0; s < GS; s++) {
        int gi = s * 32 + lane;
        float4 cc = (gi < G) ? __ldg(gc + gi) : make_float4(0, 0, 0, 0);
        float dx = qx - cc.x, dy = qy - cc.y, dz = qz - cc.z;
        float d2 = fmaf(dx, dx, fmaf(dy, dy, dz * dz));
        if (gi >= G) d2 = INF_F;
        d2c[s] = d2;
        rr[s] = cc.w;
        if (d2 < bd2) { bd2 = d2; bg = gi; }
    }
#pragma unroll
    for (int off = 16; off; off >>= 1) {
        float od = __shfl_xor_sync(0xFFFFFFFFu, bd2, off);
        int og = __shfl_xor_sync(0xFFFFFFFFu, bg, off);
        if (od < bd2 || (od == bd2 && og < bg)) { bd2 = od; bg = og; }
    }
    const int g0 = bg;  // warp-uniform

#define EVAL(POS, OUT)                                                         \
    {                                                                          \
        float4 c_ = __ldg(sx + (POS));                                         \
        float sd_ = fmaf(-qz, c_.z, fmaf(-qy, c_.y, fmaf(-qx, c_.x, c_.w)));   \
        float dxy_ = sqrtf(fmaxf(2.0f * (sd_ + qh), 0.0f));                    \
        float4 nc_ = __ldg(sn + (POS));                                        \
        float nd_ = fmaf(-uz, nc_.z, fmaf(-uy, nc_.y, fmaf(-ux, nc_.x, nc_.w)));\
        float dn_ = sqrtf(fmaxf(2.0f * (nd_ + uh), 0.0f));                     \
        (OUT) = dxy_ + 1.0f / (1.0f + __expf(-dn_));                           \
    }

    // ---- Warm-up: evaluate nearest group, extract sorted top-8 ----
    float d[K];
    int ixp[K];
    {
        float tot;
        EVAL(g0 * 32 + lane, tot);
        float v = tot;
        int vi = g0 * 32 + lane;
#pragma unroll
        for (int r = 0; r < K; r++) {
            float mv = v;
            int mi = vi;
#pragma unroll
            for (int off = 16; off; off >>= 1) {
                float ov = __shfl_xor_sync(0xFFFFFFFFu, mv, off);
                int oi = __shfl_xor_sync(0xFFFFFFFFu, mi, off);
                if (ov < mv || (ov == mv && oi < mi)) { mv = ov; mi = oi; }
            }
            d[r] = mv;
            ixp[r] = mi;
            if (vi == mi) v = INF_F;
        }
    }
    float kth = d[K - 1];

    // ---- Phase 2: group-pruned sweep ----
#pragma unroll
    for (int s = 0; s < GS; s++) {
        int gi = s * 32 + lane;
        float t = kth - 0.5f + rr[s];
        bool surv = (gi < G) && (gi != g0) && (d2c[s] < t * t);
        unsigned m = __ballot_sync(0xFFFFFFFFu, surv);
        while (m) {
            int src = __ffs(m) - 1;
            m &= m - 1;
            float dg = __shfl_sync(0xFFFFFFFFu, d2c[s], src);
            float rg = __shfl_sync(0xFFFFFFFFu, rr[s], src);
            float t2 = kth - 0.5f + rg;
            if (dg < t2 * t2) {  // warp-uniform recheck vs current kth
                int gq = s * 32 + src;
                float tot;
                EVAL(gq * 32 + lane, tot);
                unsigned m2 = __ballot_sync(0xFFFFFFFFu, tot < kth);
                while (m2) {
                    int src2 = __ffs(m2) - 1;
                    m2 &= m2 - 1;
                    float cd = __shfl_sync(0xFFFFFFFFu, tot, src2);
                    int ci = gq * 32 + src2;
#pragma unroll
                    for (int i = 0; i < K; i++) {
                        bool sw = cd < d[i];
                        float od = d[i];
                        int oi = ixp[i];
                        d[i] = sw ? cd : od;
                        ixp[i] = sw ? ci : oi;
                        cd = sw ? od : cd;
                        ci = sw ? oi : ci;
                    }
                }
                kth = d[K - 1];
            }
        }
    }
#undef EVAL

    if (lane == 0) {
        float r[K];
        float sum = 0.0f;
#pragma unroll
        for (int i = 0; i < K; i++) { r[i] = 1.0f / (d[i] + 1e-8f); sum += r[i]; }
        float inv = 1.0f / sum;
        const int* sid = g_sid + base + b * S;
        int o0 = sid[ixp[0]], o1 = sid[ixp[1]], o2 = sid[ixp[2]], o3 = sid[ixp[3]];
        int o4i = sid[ixp[4]], o5 = sid[ixp[5]], o6 = sid[ixp[6]], o7 = sid[ixp[7]];
        float4* o4 = (float4*)(g_wiv + wbase + ((size_t)b * N + n) * 16);
        o4[0] = make_float4(r[0] * inv, r[1] * inv, r[2] * inv, r[3] * inv);
        o4[1] = make_float4(r[4] * inv, r[5] * inv, r[6] * inv, r[7] * inv);
        o4[2] = make_float4(__int_as_float(o0), __int_as_float(o1),
                            __int_as_float(o2), __int_as_float(o3));
        o4[3] = make_float4(__int_as_float(o4i), __int_as_float(o5),
                            __int_as_float(o6), __int_as_float(o7));
    }
}

// ---------------------------------------------------------------------------
// Interpolate: 64 lanes (float4 channels) per query, 4 queries per block.
// ---------------------------------------------------------------------------
__global__ void __launch_bounds__(256) interp_kernel(
    const float* __restrict__ p1, const float* __restrict__ p2,
    float* __restrict__ out, int N, int S, int wbase)
{
    const int b = blockIdx.y;
    const int g = threadIdx.x >> 6;
    const int l = threadIdx.x & 63;
    const int n = blockIdx.x * 4 + g;

    const float4* wv = (const float4*)(g_wiv + wbase + ((size_t)b * N + n) * 16);
    float4 w0 = __ldg(wv + 0), w1 = __ldg(wv + 1);
    float4 f0 = __ldg(wv + 2), f1 = __ldg(wv + 3);

    const float4* __restrict__ P = (const float4*)p2 + (size_t)b * S * (C / 4);
    float4 acc;
    {
        float4 r0 = __ldg(P + (size_t)__float_as_int(f0.x) * (C / 4) + l);
        acc.x = w0.x * r0.x; acc.y = w0.x * r0.y;
        acc.z = w0.x * r0.z; acc.w = w0.x * r0.w;
    }
#define GATHER(W, IDX)                                                         \
    {                                                                          \
        float4 r_ = __ldg(P + (size_t)__float_as_int(IDX) * (C / 4) + l);      \
        acc.x = fmaf(W, r_.x, acc.x); acc.y = fmaf(W, r_.y, acc.y);            \
        acc.z = fmaf(W, r_.z, acc.z); acc.w = fmaf(W, r_.w, acc.w);            \
    }
    GATHER(w0.y, f0.y) GATHER(w0.z, f0.z) GATHER(w0.w, f0.w)
    GATHER(w1.x, f1.x) GATHER(w1.y, f1.y) GATHER(w1.z, f1.z) GATHER(w1.w, f1.w)
#undef GATHER

    const size_t qo = ((size_t)b * N + n) * (C / 4) + l;
    float4 pv = __ldg((const float4*)p1 + qo);
    float4 o;
    o.x = (fmaxf(pv.x, acc.x) + (pv.x + acc.x) * 0.5f) * 0.5f;
    o.y = (fmaxf(pv.y, acc.y) + (pv.y + acc.y) * 0.5f) * 0.5f;
    o.z = (fmaxf(pv.z, acc.z) + (pv.z + acc.z) * 0.5f) * 0.5f;
    o.w = (fmaxf(pv.w, acc.w) + (pv.w + acc.w) * 0.5f) * 0.5f;
    ((float4*)out)[qo] = o;
}

// ---------------------------------------------------------------------------
extern "C" void kernel_launch(void* const* d_in, const int* in_sizes, int n_in,
                              void* d_out, int out_size)
{
    // Classify inputs by element count (interleaved per resolution):
    // per resolution N, the two 6N tensors are xyz then nrm; 512N is feat.
    const int B = 2;
    const int Ns[4] = {16384, 4096, 1024, 256};
    const float* xyz[4] = {0, 0, 0, 0};
    const float* nrm[4] = {0, 0, 0, 0};
    const float* feat[4] = {0, 0, 0, 0};

    for (int i = 0; i < n_in; i++) {
        long long cnt = in_sizes[i];
        for (int r = 0; r < 4; r++) {
            long long small = (long long)B * Ns[r] * 3;
            long long big = (long long)B * Ns[r] * C;
            if (cnt == small) {
                if (!xyz[r]) xyz[r] = (const float*)d_in[i];
                else if (!nrm[r]) nrm[r] = (const float*)d_in[i];
                break;
            } else if (cnt == big) {
                if (!feat[r]) feat[r] = (const float*)d_in[i];
                break;
            }
        }
    }

    float* out = (float*)d_out;
    float *x1, *x2;
    cudaGetSymbolAddress((void**)&x1, g_x1);
    cudaGetSymbolAddress((void**)&x2, g_x2);

    // ---- Preprocess all coarse sets (independent of features) ----
    // stage2 coarse = xyz[1] (S=4096), stage1 coarse = xyz[2] (S=1024),
    // stage0 coarse = xyz[3] (S=256)
    pack_kernel<<<(2 * 4096 + 255) / 256, 256>>>(xyz[1], nrm[1], 2 * 4096, 4095, 0);
    pack_kernel<<<(2 * 1024 + 255) / 256, 256>>>(xyz[2], nrm[2], 2 * 1024, 1023, 8192);
    pack_kernel<<<(2 * 256 + 255) / 256, 256>>>(xyz[3], nrm[3], 2 * 256, 255, 10240);
    sort_kernel<4096, 1024><<<2, 1024>>>(0);
    sort_kernel<1024, 512><<<2, 512>>>(8192);
    sort_kernel<256, 128><<<2, 128>>>(10240);
    reorder_kernel<4096, 128><<<32, 256>>>(0, 0, 256);
    reorder_kernel<1024, 32><<<8, 256>>>(8192, 256, 64);
    reorder_kernel<256, 8><<<2, 256>>>(10240, 320, 16);

    // ---- Top-k for all stages (depends only on xyz/nrm) ----
    topk_kernel<256, 8><<<dim3(1024 / 8, B), 256>>>(xyz[2], nrm[2], 1024, 10240, 320, WOFF0);
    topk_kernel<1024, 32><<<dim3(4096 / 8, B), 256>>>(xyz[1], nrm[1], 4096, 8192, 256, WOFF1);
    topk_kernel<4096, 128><<<dim3(16384 / 8, B), 256>>>(xyz[0], nrm[0], 16384, 0, 0, WOFF2);

    // ---- Feature propagation chain ----
    interp_kernel<<<dim3(1024 / 4, B), 256>>>(feat[2], feat[3], x1, 1024, 256, WOFF0);
    interp_kernel<<<dim3(4096 / 4, B), 256>>>(feat[1], x1, x2, 4096, 1024, WOFF1);
    interp_kernel<<<dim3(16384 / 4, B), 256>>>(feat[0], x2, out, 16384, 4096, WOFF2);
}

// round 6
// speedup vs baseline: 3.2510x; 1.2670x over previous
#include <cuda_runtime.h>
#include <stdint.h>

#define K 8
#define C 256
#define INF_F __int_as_float(0x7F800000)

// ---------------------------------------------------------------------------
// Scratch. Point regions: stage2 [0,8192), stage1 [8192,10240), stage0 [10240,10752).
// Group regions: stage2 [0,256), stage1 [256,320), stage0 [320,336).
// ---------------------------------------------------------------------------
static __device__ float4 g_cx[10752];
static __device__ float4 g_cn[10752];
static __device__ unsigned long long g_code[10752];   // morton<<32 | local idx
static __device__ float4 g_sx[10752];
static __device__ float4 g_sn[10752];
static __device__ int    g_sid[10752];
static __device__ float4 g_gc[336];                   // group center + radius
static __device__ float  g_wiv[2 * 16384 * 16 + 2 * 4096 * 16 + 2 * 1024 * 16];
static __device__ float  g_x1[2 * 1024 * 256];
static __device__ float  g_x2[2 * 4096 * 256];

#define WOFF2 0
#define WOFF1 (2 * 16384 * 16)
#define WOFF0 (2 * 16384 * 16 + 2 * 4096 * 16)

// ---------------------------------------------------------------------------
__device__ __forceinline__ unsigned expand_bits(unsigned v) {
    v &= 0x3FFu;
    v = (v | (v << 16)) & 0x030000FFu;
    v = (v | (v << 8))  & 0x0300F00Fu;
    v = (v | (v << 4))  & 0x030C30C3u;
    v = (v | (v << 2))  & 0x09249249u;
    return v;
}
__device__ __forceinline__ unsigned quant10(float x) {
    float u = (x + 4.2f) * (1024.0f / 8.4f);
    u = fminf(fmaxf(u, 0.0f), 1023.0f);
    return (unsigned)u;
}

// ---------------------------------------------------------------------------
// Fused pack: all three coarse levels in one launch.
// ---------------------------------------------------------------------------
__global__ void pack_kernel(const float* __restrict__ x1p, const float* __restrict__ n1p,
                            const float* __restrict__ x2p, const float* __restrict__ n2p,
                            const float* __restrict__ x3p, const float* __restrict__ n3p)
{
    int i = blockIdx.x * 256 + threadIdx.x;
    if (i >= 10752) return;
    const float* xs;
    const float* ns;
    int j, mask;
    if (i < 8192)       { xs = x1p; ns = n1p; j = i;         mask = 4095; }
    else if (i < 10240) { xs = x2p; ns = n2p; j = i - 8192;  mask = 1023; }
    else                { xs = x3p; ns = n3p; j = i - 10240; mask = 255;  }
    float x = xs[3 * j], y = xs[3 * j + 1], z = xs[3 * j + 2];
    g_cx[i] = make_float4(x, y, z, 0.5f * (x * x + y * y + z * z));
    float a = ns[3 * j], b = ns[3 * j + 1], c = ns[3 * j + 2];
    g_cn[i] = make_float4(a, b, c, 0.5f * (a * a + b * b + c * c));
    unsigned code = (expand_bits(quant10(x)) << 2) |
                    (expand_bits(quant10(y)) << 1) |
                     expand_bits(quant10(z));
    g_code[i] = ((unsigned long long)code << 32) | (unsigned)(j & mask);
}

// ---------------------------------------------------------------------------
// Counting sort by top morton bits. One block per segment; 6 segments, 1 launch.
// ---------------------------------------------------------------------------
__global__ void __launch_bounds__(1024) csort_kernel()
{
    static const int tb[6] = {0, 4096, 8192, 9216, 10240, 10496};
    static const int ts[6] = {4096, 4096, 1024, 1024, 256, 256};
    static const int tbin[6] = {2048, 2048, 512, 512, 128, 128};
    static const int tsh[6] = {19, 19, 21, 21, 23, 23};

    __shared__ unsigned long long skeys[4096];
    __shared__ int hist[2048];

    const int seg = blockIdx.x;
    const int base = tb[seg], S = ts[seg], bins = tbin[seg], shift = tsh[seg];
    const int tid = threadIdx.x;

    for (int i = tid; i < S; i += 1024) skeys[i] = g_code[base + i];
    for (int i = tid; i < bins; i += 1024) hist[i] = 0;
    __syncthreads();
    for (int i = tid; i < S; i += 1024)
        atomicAdd(&hist[(unsigned)(skeys[i] >> 32) >> shift], 1);
    __syncthreads();
    // Blelloch exclusive scan over hist[0..bins)
    for (int dstep = 1; dstep < bins; dstep <<= 1) {
        for (int i = tid; i < bins / (2 * dstep); i += 1024) {
            int idx = (i + 1) * 2 * dstep - 1;
            hist[idx] += hist[idx - dstep];
        }
        __syncthreads();
    }
    if (tid == 0) hist[bins - 1] = 0;
    __syncthreads();
    for (int dstep = bins >> 1; dstep >= 1; dstep >>= 1) {
        for (int i = tid; i < bins / (2 * dstep); i += 1024) {
            int idx = (i + 1) * 2 * dstep - 1;
            int t = hist[idx - dstep];
            hist[idx - dstep] = hist[idx];
            hist[idx] += t;
        }
        __syncthreads();
    }
    for (int i = tid; i < S; i += 1024) {
        unsigned long long key = skeys[i];
        int bin = (unsigned)(key >> 32) >> shift;
        int pos = atomicAdd(&hist[bin], 1);
        g_code[base + pos] = key;
    }
}

// ---------------------------------------------------------------------------
// Reorder into sorted arrays + per-32-point bounding spheres. One launch.
// ---------------------------------------------------------------------------
__global__ void __launch_bounds__(256) reorder_kernel()
{
    int w = (blockIdx.x * 256 + threadIdx.x) >> 5;   // global warp id, 0..335
    int lane = threadIdx.x & 31;
    if (w >= 336) return;
    int base, gbase, G, S, w0;
    if (w < 256)      { base = 0;     gbase = 0;   G = 128; S = 4096; w0 = 0;   }
    else if (w < 320) { base = 8192;  gbase = 256; G = 32;  S = 1024; w0 = 256; }
    else              { base = 10240; gbase = 320; G = 8;   S = 256;  w0 = 320; }
    int lw = w - w0;
    int bseg = lw / G, gi = lw % G;
    int sb = base + bseg * S;

    unsigned long long key = g_code[sb + gi * 32 + lane];
    int li = (int)(unsigned)key;
    float4 v = g_cx[sb + li];
    int dst = sb + gi * 32 + lane;
    g_sx[dst] = v;
    g_sn[dst] = g_cn[sb + li];
    g_sid[dst] = li;

    float mnx = v.x, mxx = v.x, mny = v.y, mxy = v.y, mnz = v.z, mxz = v.z;
#pragma unroll
    for (int off = 16; off; off >>= 1) {
        mnx = fminf(mnx, __shfl_xor_sync(0xFFFFFFFFu, mnx, off));
        mxx = fmaxf(mxx, __shfl_xor_sync(0xFFFFFFFFu, mxx, off));
        mny = fminf(mny, __shfl_xor_sync(0xFFFFFFFFu, mny, off));
        mxy = fmaxf(mxy, __shfl_xor_sync(0xFFFFFFFFu, mxy, off));
        mnz = fminf(mnz, __shfl_xor_sync(0xFFFFFFFFu, mnz, off));
        mxz = fmaxf(mxz, __shfl_xor_sync(0xFFFFFFFFu, mxz, off));
    }
    float cxc = (mnx + mxx) * 0.5f, cyc = (mny + mxy) * 0.5f, czc = (mnz + mxz) * 0.5f;
    float dx = v.x - cxc, dy = v.y - cyc, dz = v.z - czc;
    float d2 = fmaf(dx, dx, fmaf(dy, dy, dz * dz));
#pragma unroll
    for (int off = 16; off; off >>= 1)
        d2 = fmaxf(d2, __shfl_xor_sync(0xFFFFFFFFu, d2, off));
    if (lane == 0) g_gc[gbase + lw] = make_float4(cxc, cyc, czc, sqrtf(d2));
}

// ---------------------------------------------------------------------------
// topk: warp per query, group-pruned sweep, lazy normal-distance eval.
// ---------------------------------------------------------------------------
template <int S, int G>
__global__ void __launch_bounds__(256) topk_kernel(
    const float* __restrict__ xyzF, const float* __restrict__ nrmF,
    int N, int base, int gbase, int wbase)
{
    const int lane = threadIdx.x & 31;
    const int b = blockIdx.y;
    const int n = blockIdx.x * 8 + (threadIdx.x >> 5);
    if (n >= N) return;

    const float4* __restrict__ sx = g_sx + base + b * S;
    const float4* __restrict__ sn = g_sn + base + b * S;
    const float4* __restrict__ gc = g_gc + gbase + b * G;

    const float* p = xyzF + ((size_t)b * N + n) * 3;
    const float qx = p[0], qy = p[1], qz = p[2];
    const float qh = 0.5f * (qx * qx + qy * qy + qz * qz);
    const float* q = nrmF + ((size_t)b * N + n) * 3;
    const float ux = q[0], uy = q[1], uz = q[2];
    const float uh = 0.5f * (ux * ux + uy * uy + uz * uz);

    constexpr int GS = (G + 31) / 32;
    float d2c[GS], rr[GS];

    // ---- Phase 1: distances to group centers; nearest group ----
    float bd2 = INF_F;
    int bg = 0;
#pragma unroll
    for (int s = 0; s < GS; s++) {
        int gi = s * 32 + lane;
        float4 cc = (gi < G) ? __ldg(gc + gi) : make_float4(0, 0, 0, 0);
        float dx = qx - cc.x, dy = qy - cc.y, dz = qz - cc.z;
        float d2 = fmaf(dx, dx, fmaf(dy, dy, dz * dz));
        if (gi >= G) d2 = INF_F;
        d2c[s] = d2;
        rr[s] = cc.w;
        if (d2 < bd2) { bd2 = d2; bg = gi; }
    }
#pragma unroll
    for (int off = 16; off; off >>= 1) {
        float od = __shfl_xor_sync(0xFFFFFFFFu, bd2, off);
        int og = __shfl_xor_sync(0xFFFFFFFFu, bg, off);
        if (od < bd2 || (od == bd2 && og < bg)) { bd2 = od; bg = og; }
    }
    const int g0 = bg;  // warp-uniform

    // ---- Warm-up: full eval of nearest group, sorted top-8 via shfl-min ----
    float d[K];
    int ixp[K];
    {
        int pos = g0 * 32 + lane;
        float4 c = __ldg(sx + pos);
        float sd = fmaf(-qz, c.z, fmaf(-qy, c.y, fmaf(-qx, c.x, c.w)));
        float dxy = sqrtf(fmaxf(2.0f * (sd + qh), 0.0f));
        float4 nc = __ldg(sn + pos);
        float nd = fmaf(-uz, nc.z, fmaf(-uy, nc.y, fmaf(-ux, nc.x, nc.w)));
        float dn = sqrtf(fmaxf(2.0f * (nd + uh), 0.0f));
        float v = dxy + 1.0f / (1.0f + __expf(-dn));
        int vi = pos;
#pragma unroll
        for (int r = 0; r < K; r++) {
            float mv = v;
            int mi = vi;
#pragma unroll
            for (int off = 16; off; off >>= 1) {
                float ov = __shfl_xor_sync(0xFFFFFFFFu, mv, off);
                int oi = __shfl_xor_sync(0xFFFFFFFFu, mi, off);
                if (ov < mv || (ov == mv && oi < mi)) { mv = ov; mi = oi; }
            }
            d[r] = mv;
            ixp[r] = mi;
            if (vi == mi) v = INF_F;
        }
    }
    float kth = d[K - 1];
    float kth05 = kth - 0.5f;

    // ---- Phase 2: group-pruned sweep with lazy nrm eval ----
#pragma unroll
    for (int s = 0; s < GS; s++) {
        int gi = s * 32 + lane;
        float t = kth05 + rr[s];
        bool surv = (gi < G) && (gi != g0) && (d2c[s] < t * t);
        unsigned m = __ballot_sync(0xFFFFFFFFu, surv);
        while (m) {
            int src = __ffs(m) - 1;
            m &= m - 1;
            float dg = __shfl_sync(0xFFFFFFFFu, d2c[s], src);
            float rg = __shfl_sync(0xFFFFFFFFu, rr[s], src);
            float t2 = kth05 + rg;
            if (dg < t2 * t2) {                    // warp-uniform recheck
                int pos = (s * 32 + src) * 32 + lane;
                float4 c = __ldg(sx + pos);
                float sd = fmaf(-qz, c.z, fmaf(-qy, c.y, fmaf(-qx, c.x, c.w)));
                float dxy = sqrtf(fmaxf(2.0f * (sd + qh), 0.0f));
                bool maybe = dxy < kth05;          // dxy + 0.5 < kth
                unsigned mm = __ballot_sync(0xFFFFFFFFu, maybe);
                if (mm) {
                    float tot = INF_F;
                    if (maybe) {
                        float4 nc = __ldg(sn + pos);
                        float nd = fmaf(-uz, nc.z,
                                        fmaf(-uy, nc.y, fmaf(-ux, nc.x, nc.w)));
                        float dn = sqrtf(fmaxf(2.0f * (nd + uh), 0.0f));
                        tot = dxy + 1.0f / (1.0f + __expf(-dn));
                    }
                    unsigned m2 = __ballot_sync(0xFFFFFFFFu, tot < kth);
                    while (m2) {
                        int src2 = __ffs(m2) - 1;
                        m2 &= m2 - 1;
                        float cd = __shfl_sync(0xFFFFFFFFu, tot, src2);
                        int ci = pos - lane + src2;
#pragma unroll
                        for (int i = 0; i < K; i++) {
                            bool sw = cd < d[i];
                            float od = d[i];
                            int oi = ixp[i];
                            d[i] = sw ? cd : od;
                            ixp[i] = sw ? ci : oi;
                            cd = sw ? od : cd;
                            ci = sw ? oi : ci;
                        }
                    }
                    kth = d[K - 1];
                    kth05 = kth - 0.5f;
                }
            }
        }
    }

    if (lane == 0) {
        float r[K];
        float sum = 0.0f;
#pragma unroll
        for (int i = 0; i < K; i++) { r[i] = 1.0f / (d[i] + 1e-8f); sum += r[i]; }
        float inv = 1.0f / sum;
        const int* sid = g_sid + base + b * S;
        int o0 = sid[ixp[0]], o1 = sid[ixp[1]], o2 = sid[ixp[2]], o3 = sid[ixp[3]];
        int o4i = sid[ixp[4]], o5 = sid[ixp[5]], o6 = sid[ixp[6]], o7 = sid[ixp[7]];
        float4* o4 = (float4*)(g_wiv + wbase + ((size_t)b * N + n) * 16);
        o4[0] = make_float4(r[0] * inv, r[1] * inv, r[2] * inv, r[3] * inv);
        o4[1] = make_float4(r[4] * inv, r[5] * inv, r[6] * inv, r[7] * inv);
        o4[2] = make_float4(__int_as_float(o0), __int_as_float(o1),
                            __int_as_float(o2), __int_as_float(o3));
        o4[3] = make_float4(__int_as_float(o4i), __int_as_float(o5),
                            __int_as_float(o6), __int_as_float(o7));
    }
}

// ---------------------------------------------------------------------------
// Interpolate: 64 lanes (float4 channels) per query, 4 queries per block.
// ---------------------------------------------------------------------------
__global__ void __launch_bounds__(256) interp_kernel(
    const float* __restrict__ p1, const float* __restrict__ p2,
    float* __restrict__ out, int N, int S, int wbase)
{
    const int b = blockIdx.y;
    const int g = threadIdx.x >> 6;
    const int l = threadIdx.x & 63;
    const int n = blockIdx.x * 4 + g;

    const float4* wv = (const float4*)(g_wiv + wbase + ((size_t)b * N + n) * 16);
    float4 w0 = __ldg(wv + 0), w1 = __ldg(wv + 1);
    float4 f0 = __ldg(wv + 2), f1 = __ldg(wv + 3);

    const float4* __restrict__ P = (const float4*)p2 + (size_t)b * S * (C / 4);
    float4 acc;
    {
        float4 r0 = __ldg(P + (size_t)__float_as_int(f0.x) * (C / 4) + l);
        acc.x = w0.x * r0.x; acc.y = w0.x * r0.y;
        acc.z = w0.x * r0.z; acc.w = w0.x * r0.w;
    }
#define GATHER(W, IDX)                                                         \
    {                                                                          \
        float4 r_ = __ldg(P + (size_t)__float_as_int(IDX) * (C / 4) + l);      \
        acc.x = fmaf(W, r_.x, acc.x); acc.y = fmaf(W, r_.y, acc.y);            \
        acc.z = fmaf(W, r_.z, acc.z); acc.w = fmaf(W, r_.w, acc.w);            \
    }
    GATHER(w0.y, f0.y) GATHER(w0.z, f0.z) GATHER(w0.w, f0.w)
    GATHER(w1.x, f1.x) GATHER(w1.y, f1.y) GATHER(w1.z, f1.z) GATHER(w1.w, f1.w)
#undef GATHER

    const size_t qo = ((size_t)b * N + n) * (C / 4) + l;
    float4 pv = __ldg((const float4*)p1 + qo);
    float4 o;
    o.x = (fmaxf(pv.x, acc.x) + (pv.x + acc.x) * 0.5f) * 0.5f;
    o.y = (fmaxf(pv.y, acc.y) + (pv.y + acc.y) * 0.5f) * 0.5f;
    o.z = (fmaxf(pv.z, acc.z) + (pv.z + acc.z) * 0.5f) * 0.5f;
    o.w = (fmaxf(pv.w, acc.w) + (pv.w + acc.w) * 0.5f) * 0.5f;
    ((float4*)out)[qo] = o;
}

// ---------------------------------------------------------------------------
extern "C" void kernel_launch(void* const* d_in, const int* in_sizes, int n_in,
                              void* d_out, int out_size)
{
    // Classify inputs by element count (interleaved per resolution):
    // per resolution N, the two 6N tensors are xyz then nrm; 512N is feat.
    const int B = 2;
    const int Ns[4] = {16384, 4096, 1024, 256};
    const float* xyz[4] = {0, 0, 0, 0};
    const float* nrm[4] = {0, 0, 0, 0};
    const float* feat[4] = {0, 0, 0, 0};

    for (int i = 0; i < n_in; i++) {
        long long cnt = in_sizes[i];
        for (int r = 0; r < 4; r++) {
            long long small = (long long)B * Ns[r] * 3;
            long long big = (long long)B * Ns[r] * C;
            if (cnt == small) {
                if (!xyz[r]) xyz[r] = (const float*)d_in[i];
                else if (!nrm[r]) nrm[r] = (const float*)d_in[i];
                break;
            } else if (cnt == big) {
                if (!feat[r]) feat[r] = (const float*)d_in[i];
                break;
            }
        }
    }

    float* out = (float*)d_out;
    float *x1, *x2;
    cudaGetSymbolAddress((void**)&x1, g_x1);
    cudaGetSymbolAddress((void**)&x2, g_x2);

    // ---- Preprocess all coarse sets (3 fused launches) ----
    pack_kernel<<<(10752 + 255) / 256, 256>>>(xyz[1], nrm[1], xyz[2], nrm[2],
                                              xyz[3], nrm[3]);
    csort_kernel<<<6, 1024>>>();
    reorder_kernel<<<42, 256>>>();

    // ---- Top-k for all stages ----
    topk_kernel<256, 8><<<dim3(1024 / 8, B), 256>>>(xyz[2], nrm[2], 1024, 10240, 320, WOFF0);
    topk_kernel<1024, 32><<<dim3(4096 / 8, B), 256>>>(xyz[1], nrm[1], 4096, 8192, 256, WOFF1);
    topk_kernel<4096, 128><<<dim3(16384 / 8, B), 256>>>(xyz[0], nrm[0], 16384, 0, 0, WOFF2);

    // ---- Feature propagation chain ----
    interp_kernel<<<dim3(1024 / 4, B), 256>>>(feat[2], feat[3], x1, 1024, 256, WOFF0);
    interp_kernel<<<dim3(4096 / 4, B), 256>>>(feat[1], x1, x2, 4096, 1024, WOFF1);
    interp_kernel<<<dim3(16384 / 4, B), 256>>>(feat[0], x2, out, 16384, 4096, WOFF2);
}

// round 7
// speedup vs baseline: 3.8130x; 1.1729x over previous
#include <cuda_runtime.h>
#include <stdint.h>

#define K 8
#define C 256
#define INF_F __int_as_float(0x7F800000)

// ---------------------------------------------------------------------------
// Scratch. Point regions: stage2 [0,8192), stage1 [8192,10240), stage0 [10240,10752).
// Group regions: stage2 [0,256), stage1 [256,320), stage0 [320,336).
// ---------------------------------------------------------------------------
static __device__ float4 g_cx[10752];
static __device__ float4 g_cn[10752];
static __device__ unsigned long long g_code[10752];   // morton<<32 | local idx
static __device__ float4 g_sx[10752];
static __device__ float4 g_sn[10752];
static __device__ int    g_sid[10752];
static __device__ float4 g_gc[336];                   // group center + radius
static __device__ float  g_wiv[2 * 16384 * 16 + 2 * 4096 * 16 + 2 * 1024 * 16];
static __device__ float  g_x1[2 * 1024 * 256];
static __device__ float  g_x2[2 * 4096 * 256];

#define WOFF2 0
#define WOFF1 (2 * 16384 * 16)
#define WOFF0 (2 * 16384 * 16 + 2 * 4096 * 16)

// ---------------------------------------------------------------------------
__device__ __forceinline__ unsigned expand_bits(unsigned v) {
    v &= 0x3FFu;
    v = (v | (v << 16)) & 0x030000FFu;
    v = (v | (v << 8))  & 0x0300F00Fu;
    v = (v | (v << 4))  & 0x030C30C3u;
    v = (v | (v << 2))  & 0x09249249u;
    return v;
}
__device__ __forceinline__ unsigned quant10(float x) {
    float u = (x + 4.2f) * (1024.0f / 8.4f);
    u = fminf(fmaxf(u, 0.0f), 1023.0f);
    return (unsigned)u;
}

// ---------------------------------------------------------------------------
// Fused pack: all three coarse levels in one launch.
// ---------------------------------------------------------------------------
__global__ void pack_kernel(const float* __restrict__ x1p, const float* __restrict__ n1p,
                            const float* __restrict__ x2p, const float* __restrict__ n2p,
                            const float* __restrict__ x3p, const float* __restrict__ n3p)
{
    int i = blockIdx.x * 256 + threadIdx.x;
    if (i >= 10752) return;
    const float* xs;
    const float* ns;
    int j, mask;
    if (i < 8192)       { xs = x1p; ns = n1p; j = i;         mask = 4095; }
    else if (i < 10240) { xs = x2p; ns = n2p; j = i - 8192;  mask = 1023; }
    else                { xs = x3p; ns = n3p; j = i - 10240; mask = 255;  }
    float x = xs[3 * j], y = xs[3 * j + 1], z = xs[3 * j + 2];
    g_cx[i] = make_float4(x, y, z, 0.5f * (x * x + y * y + z * z));
    float a = ns[3 * j], b = ns[3 * j + 1], c = ns[3 * j + 2];
    g_cn[i] = make_float4(a, b, c, 0.5f * (a * a + b * b + c * c));
    unsigned code = (expand_bits(quant10(x)) << 2) |
                    (expand_bits(quant10(y)) << 1) |
                     expand_bits(quant10(z));
    g_code[i] = ((unsigned long long)code << 32) | (unsigned)(j & mask);
}

// ---------------------------------------------------------------------------
// Counting sort by top morton bits + fused reorder & bounding spheres.
// One block per segment; 6 segments, 1 launch.
// ---------------------------------------------------------------------------
__global__ void __launch_bounds__(1024) csort_kernel()
{
    static const int tb[6]   = {0, 4096, 8192, 9216, 10240, 10496};
    static const int ts[6]   = {4096, 4096, 1024, 1024, 256, 256};
    static const int tbin[6] = {2048, 2048, 512, 512, 128, 128};
    static const int tsh[6]  = {19, 19, 21, 21, 23, 23};
    static const int tgb[6]  = {0, 128, 256, 288, 320, 328};

    __shared__ unsigned long long skeys[4096];
    __shared__ int hist[2048];

    const int seg = blockIdx.x;
    const int base = tb[seg], S = ts[seg], bins = tbin[seg], shift = tsh[seg];
    const int tid = threadIdx.x;

    for (int i = tid; i < S; i += 1024) skeys[i] = g_code[base + i];
    for (int i = tid; i < bins; i += 1024) hist[i] = 0;
    __syncthreads();
    for (int i = tid; i < S; i += 1024)
        atomicAdd(&hist[(unsigned)(skeys[i] >> 32) >> shift], 1);
    __syncthreads();
    // Blelloch exclusive scan
    for (int dstep = 1; dstep < bins; dstep <<= 1) {
        for (int i = tid; i < bins / (2 * dstep); i += 1024) {
            int idx = (i + 1) * 2 * dstep - 1;
            hist[idx] += hist[idx - dstep];
        }
        __syncthreads();
    }
    if (tid == 0) hist[bins - 1] = 0;
    __syncthreads();
    for (int dstep = bins >> 1; dstep >= 1; dstep >>= 1) {
        for (int i = tid; i < bins / (2 * dstep); i += 1024) {
            int idx = (i + 1) * 2 * dstep - 1;
            int t = hist[idx - dstep];
            hist[idx - dstep] = hist[idx];
            hist[idx] += t;
        }
        __syncthreads();
    }
    for (int i = tid; i < S; i += 1024) {
        unsigned long long key = skeys[i];
        int bin = (unsigned)(key >> 32) >> shift;
        int pos = atomicAdd(&hist[bin], 1);
        g_code[base + pos] = key;   // scatter (global; same block reads back)
    }
    __syncthreads();

    // ---- fused reorder + bounding spheres ----
    int warp = tid >> 5, lane = tid & 31;
    int nG = S / 32;
    for (int g = warp; g < nG; g += 32) {
        unsigned long long key = g_code[base + g * 32 + lane];
        int li = (int)(unsigned)key;
        float4 v = g_cx[base + li];
        int dst = base + g * 32 + lane;
        g_sx[dst] = v;
        g_sn[dst] = g_cn[base + li];
        g_sid[dst] = li;

        float mnx = v.x, mxx = v.x, mny = v.y, mxy = v.y, mnz = v.z, mxz = v.z;
#pragma unroll
        for (int off = 16; off; off >>= 1) {
            mnx = fminf(mnx, __shfl_xor_sync(0xFFFFFFFFu, mnx, off));
            mxx = fmaxf(mxx, __shfl_xor_sync(0xFFFFFFFFu, mxx, off));
            mny = fminf(mny, __shfl_xor_sync(0xFFFFFFFFu, mny, off));
            mxy = fmaxf(mxy, __shfl_xor_sync(0xFFFFFFFFu, mxy, off));
            mnz = fminf(mnz, __shfl_xor_sync(0xFFFFFFFFu, mnz, off));
            mxz = fmaxf(mxz, __shfl_xor_sync(0xFFFFFFFFu, mxz, off));
        }
        float cxc = (mnx + mxx) * 0.5f, cyc = (mny + mxy) * 0.5f, czc = (mnz + mxz) * 0.5f;
        float dx = v.x - cxc, dy = v.y - cyc, dz = v.z - czc;
        float d2 = fmaf(dx, dx, fmaf(dy, dy, dz * dz));
#pragma unroll
        for (int off = 16; off; off >>= 1)
            d2 = fmaxf(d2, __shfl_xor_sync(0xFFFFFFFFu, d2, off));
        if (lane == 0) g_gc[tgb[seg] + g] = make_float4(cxc, cyc, czc, sqrtf(d2));
    }
}

// ---------------------------------------------------------------------------
// topk per-query device function: warp per query, sphere-pruned sweep.
// ---------------------------------------------------------------------------
template <int S, int G>
__device__ __forceinline__ void topk_query(
    const float* __restrict__ xyzF, const float* __restrict__ nrmF,
    int N, int base, int gbase, int wbase, int b, int n, int lane)
{
    const float4* __restrict__ sx = g_sx + base + b * S;
    const float4* __restrict__ sn = g_sn + base + b * S;
    const float4* __restrict__ gc = g_gc + gbase + b * G;

    const float* p = xyzF + ((size_t)b * N + n) * 3;
    const float qx = p[0], qy = p[1], qz = p[2];
    const float qh = 0.5f * (qx * qx + qy * qy + qz * qz);
    const float* q = nrmF + ((size_t)b * N + n) * 3;
    const float ux = q[0], uy = q[1], uz = q[2];
    const float uh = 0.5f * (ux * ux + uy * uy + uz * uz);

    constexpr int GS = (G + 31) / 32;
    float sg[GS];   // sqrt(center dist) - radius  (lower bound to any group point)

    // ---- Phase 1: group distances; nearest group via one REDUX.MIN ----
    float bd2 = INF_F;
    unsigned bcode = 0;
#pragma unroll
    for (int s = 0; s < GS; s++) {
        int gi = s * 32 + lane;
        float4 cc = make_float4(0.0f, 0.0f, 0.0f, 0.0f);
        if (G >= 32 || gi < G) cc = __ldg(gc + gi);
        float dx = qx - cc.x, dy = qy - cc.y, dz = qz - cc.z;
        float d2 = fmaf(dx, dx, fmaf(dy, dy, dz * dz));
        float sgv = sqrtf(d2) - cc.w;
        if (!(G >= 32 || gi < G)) { d2 = INF_F; sgv = INF_F; }
        sg[s] = sgv;
        if (d2 < bd2) { bd2 = d2; bcode = (unsigned)(s << 5) | lane; }
    }
    unsigned kmin = (__float_as_uint(bd2) & 0xFFFFFF80u) | bcode;
    kmin = __reduce_min_sync(0xFFFFFFFFu, kmin);
    const int g0 = (int)(((kmin >> 5) & 3u) * 32u + (kmin & 31u));

    float d[K];
    int ixp[K];
#pragma unroll
    for (int i = 0; i < K; i++) { d[i] = INF_F; ixp[i] = 0; }

#define INSERT_POPS(MASK, TOTV, POSBASE)                                       \
    while (MASK) {                                                             \
        int sp_ = __ffs(MASK) - 1;                                             \
        MASK &= MASK - 1;                                                      \
        float cd_ = __shfl_sync(0xFFFFFFFFu, TOTV, sp_);                       \
        int ci_ = (POSBASE) + sp_;                                             \
        _Pragma("unroll") for (int i_ = 0; i_ < K; i_++)                       \
        {                                                                      \
            bool sw_ = cd_ < d[i_];                                            \
            float od_ = d[i_];                                                 \
            int oi_ = ixp[i_];                                                 \
            d[i_] = sw_ ? cd_ : od_;                                           \
            ixp[i_] = sw_ ? ci_ : oi_;                                         \
            cd_ = sw_ ? od_ : cd_;                                             \
            ci_ = sw_ ? oi_ : ci_;                                             \
        }                                                                      \
    }

    // ---- Warm-up: eval nearest group; ub = max of quad minima (>= 8th) ----
    {
        int pos = g0 * 32 + lane;
        float4 c = __ldg(sx + pos);
        float sd = fmaf(-qz, c.z, fmaf(-qy, c.y, fmaf(-qx, c.x, c.w)));
        float dxy = sqrtf(fmaxf(2.0f * (sd + qh), 0.0f));
        float4 nc = __ldg(sn + pos);
        float nd = fmaf(-uz, nc.z, fmaf(-uy, nc.y, fmaf(-ux, nc.x, nc.w)));
        float dn = sqrtf(fmaxf(2.0f * (nd + uh), 0.0f));
        float tot = dxy + 1.0f / (1.0f + __expf(-dn));

        float qm = fminf(tot, __shfl_xor_sync(0xFFFFFFFFu, tot, 1));
        qm = fminf(qm, __shfl_xor_sync(0xFFFFFFFFu, qm, 2));
        float ub = fmaxf(qm, __shfl_xor_sync(0xFFFFFFFFu, qm, 4));
        ub = fmaxf(ub, __shfl_xor_sync(0xFFFFFFFFu, ub, 8));
        ub = fmaxf(ub, __shfl_xor_sync(0xFFFFFFFFu, ub, 16));

        unsigned m2 = __ballot_sync(0xFFFFFFFFu, tot <= ub);
        INSERT_POPS(m2, tot, g0 * 32)
    }
    float kth = d[K - 1];
    float kth05 = kth - 0.5f;

    // ---- Phase 2: sphere-pruned sweep, lazy nrm eval ----
#pragma unroll
    for (int s = 0; s < GS; s++) {
        bool surv = (sg[s] < kth05) && (s * 32 + lane != g0);
        unsigned m = __ballot_sync(0xFFFFFFFFu, surv);
        while (m) {
            int src = __ffs(m) - 1;
            m &= m - 1;
            float sgl = __shfl_sync(0xFFFFFFFFu, sg[s], src);
            if (sgl < kth05) {                       // warp-uniform recheck
                int pos = (s * 32 + src) * 32 + lane;
                float4 c = __ldg(sx + pos);
                float sd = fmaf(-qz, c.z, fmaf(-qy, c.y, fmaf(-qx, c.x, c.w)));
                float dxy = sqrtf(fmaxf(2.0f * (sd + qh), 0.0f));
                float tot = INF_F;
                if (dxy < kth05) {                   // only then nrm eval
                    float4 nc = __ldg(sn + pos);
                    float nd = fmaf(-uz, nc.z,
                                    fmaf(-uy, nc.y, fmaf(-ux, nc.x, nc.w)));
                    float dn = sqrtf(fmaxf(2.0f * (nd + uh), 0.0f));
                    tot = dxy + 1.0f / (1.0f + __expf(-dn));
                }
                unsigned m2 = __ballot_sync(0xFFFFFFFFu, tot < kth);
                if (m2) {
                    INSERT_POPS(m2, tot, pos - lane)
                    kth = d[K - 1];
                    kth05 = kth - 0.5f;
                }
            }
        }
    }
#undef INSERT_POPS

    if (lane == 0) {
        float r[K];
        float sum = 0.0f;
#pragma unroll
        for (int i = 0; i < K; i++) { r[i] = 1.0f / (d[i] + 1e-8f); sum += r[i]; }
        float inv = 1.0f / sum;
        const int* sid = g_sid + base + b * S;
        int o0 = sid[ixp[0]], o1 = sid[ixp[1]], o2 = sid[ixp[2]], o3 = sid[ixp[3]];
        int o4i = sid[ixp[4]], o5 = sid[ixp[5]], o6 = sid[ixp[6]], o7 = sid[ixp[7]];
        float4* o4 = (float4*)(g_wiv + wbase + ((size_t)b * N + n) * 16);
        o4[0] = make_float4(r[0] * inv, r[1] * inv, r[2] * inv, r[3] * inv);
        o4[1] = make_float4(r[4] * inv, r[5] * inv, r[6] * inv, r[7] * inv);
        o4[2] = make_float4(__int_as_float(o0), __int_as_float(o1),
                            __int_as_float(o2), __int_as_float(o3));
        o4[3] = make_float4(__int_as_float(o4i), __int_as_float(o5),
                            __int_as_float(o6), __int_as_float(o7));
    }
}

// ---------------------------------------------------------------------------
// Fused topk: all three stages in one launch. Stage2 blocks first.
// blocks: [0,4096) stage2, [4096,5120) stage1, [5120,5376) stage0.
// ---------------------------------------------------------------------------
__global__ void __launch_bounds__(256, 6) topk_fused(
    const float* __restrict__ x0, const float* __restrict__ n0,
    const float* __restrict__ x1, const float* __restrict__ n1,
    const float* __restrict__ x2, const float* __restrict__ n2)
{
    const int bid = blockIdx.x;
    const int warp = threadIdx.x >> 5;
    const int lane = threadIdx.x & 31;
    if (bid < 4096) {
        int lb = bid, b = lb >> 11, n = (lb & 2047) * 8 + warp;
        topk_query<4096, 128>(x0, n0, 16384, 0, 0, WOFF2, b, n, lane);
    } else if (bid < 5120) {
        int lb = bid - 4096, b = lb >> 9, n = (lb & 511) * 8 + warp;
        topk_query<1024, 32>(x1, n1, 4096, 8192, 256, WOFF1, b, n, lane);
    } else {
        int lb = bid - 5120, b = lb >> 7, n = (lb & 127) * 8 + warp;
        topk_query<256, 8>(x2, n2, 1024, 10240, 320, WOFF0, b, n, lane);
    }
}

// ---------------------------------------------------------------------------
// Interpolate: 64 lanes (float4 channels) per query, 4 queries per block.
// ---------------------------------------------------------------------------
__global__ void __launch_bounds__(256) interp_kernel(
    const float* __restrict__ p1, const float* __restrict__ p2,
    float* __restrict__ out, int N, int S, int wbase)
{
    const int b = blockIdx.y;
    const int g = threadIdx.x >> 6;
    const int l = threadIdx.x & 63;
    const int n = blockIdx.x * 4 + g;

    const float4* wv = (const float4*)(g_wiv + wbase + ((size_t)b * N + n) * 16);
    float4 w0 = __ldg(wv + 0), w1 = __ldg(wv + 1);
    float4 f0 = __ldg(wv + 2), f1 = __ldg(wv + 3);

    const float4* __restrict__ P = (const float4*)p2 + (size_t)b * S * (C / 4);
    float4 acc;
    {
        float4 r0 = __ldg(P + (size_t)__float_as_int(f0.x) * (C / 4) + l);
        acc.x = w0.x * r0.x; acc.y = w0.x * r0.y;
        acc.z = w0.x * r0.z; acc.w = w0.x * r0.w;
    }
#define GATHER(W, IDX)                                                         \
    {                                                                          \
        float4 r_ = __ldg(P + (size_t)__float_as_int(IDX) * (C / 4) + l);      \
        acc.x = fmaf(W, r_.x, acc.x); acc.y = fmaf(W, r_.y, acc.y);            \
        acc.z = fmaf(W, r_.z, acc.z); acc.w = fmaf(W, r_.w, acc.w);            \
    }
    GATHER(w0.y, f0.y) GATHER(w0.z, f0.z) GATHER(w0.w, f0.w)
    GATHER(w1.x, f1.x) GATHER(w1.y, f1.y) GATHER(w1.z, f1.z) GATHER(w1.w, f1.w)
#undef GATHER

    const size_t qo = ((size_t)b * N + n) * (C / 4) + l;
    float4 pv = __ldg((const float4*)p1 + qo);
    float4 o;
    o.x = (fmaxf(pv.x, acc.x) + (pv.x + acc.x) * 0.5f) * 0.5f;
    o.y = (fmaxf(pv.y, acc.y) + (pv.y + acc.y) * 0.5f) * 0.5f;
    o.z = (fmaxf(pv.z, acc.z) + (pv.z + acc.z) * 0.5f) * 0.5f;
    o.w = (fmaxf(pv.w, acc.w) + (pv.w + acc.w) * 0.5f) * 0.5f;
    ((float4*)out)[qo] = o;
}

// ---------------------------------------------------------------------------
extern "C" void kernel_launch(void* const* d_in, const int* in_sizes, int n_in,
                              void* d_out, int out_size)
{
    const int B = 2;
    const int Ns[4] = {16384, 4096, 1024, 256};
    const float* xyz[4] = {0, 0, 0, 0};
    const float* nrm[4] = {0, 0, 0, 0};
    const float* feat[4] = {0, 0, 0, 0};

    for (int i = 0; i < n_in; i++) {
        long long cnt = in_sizes[i];
        for (int r = 0; r < 4; r++) {
            long long small = (long long)B * Ns[r] * 3;
            long long big = (long long)B * Ns[r] * C;
            if (cnt == small) {
                if (!xyz[r]) xyz[r] = (const float*)d_in[i];
                else if (!nrm[r]) nrm[r] = (const float*)d_in[i];
                break;
            } else if (cnt == big) {
                if (!feat[r]) feat[r] = (const float*)d_in[i];
                break;
            }
        }
    }

    float* out = (float*)d_out;
    float *x1, *x2;
    cudaGetSymbolAddress((void**)&x1, g_x1);
    cudaGetSymbolAddress((void**)&x2, g_x2);

    // ---- Preprocess (2 launches) ----
    pack_kernel<<<42, 256>>>(xyz[1], nrm[1], xyz[2], nrm[2], xyz[3], nrm[3]);
    csort_kernel<<<6, 1024>>>();

    // ---- All top-k stages in one launch ----
    topk_fused<<<5376, 256>>>(xyz[0], nrm[0], xyz[1], nrm[1], xyz[2], nrm[2]);

    // ---- Feature propagation chain ----
    interp_kernel<<<dim3(1024 / 4, B), 256>>>(feat[2], feat[3], x1, 1024, 256, WOFF0);
    interp_kernel<<<dim3(4096 / 4, B), 256>>>(feat[1], x1, x2, 4096, 1024, WOFF1);
    interp_kernel<<<dim3(16384 / 4, B), 256>>>(feat[0], x2, out, 16384, 4096, WOFF2);
}